// round 4
// baseline (speedup 1.0000x reference)
#include <cuda_runtime.h>
#include <cuda_bf16.h>
#include <math.h>
#include <stdint.h>

// Problem constants (dataset-fixed shapes)
#define B_SZ   1024
#define N_SZ   8192
#define M_C    3000        // N_COMMON
#define MP     3008        // padded M (multiple of 32, zero-filled tail)
#define EPS_B  1e-8f

// ---------------- scratch (no runtime allocation allowed) ----------------
__device__ __align__(16) __nv_bfloat16 g_y1c[B_SZ * MP];
__device__ __align__(16) __nv_bfloat16 g_y2c[B_SZ * MP];
__device__ float g_sq1[B_SZ];
__device__ float g_sq2[B_SZ];

// deterministic common-grid abscissa: IDENTICAL rounding at every use site
__device__ __forceinline__ float xc_of(int m, float xmin, float range, float inv_m1) {
    float t = (m == M_C - 1) ? 1.0f : (float)m * inv_m1;
    return __fmaf_rn(t, range, xmin);
}

// ---------------- kernel 1: interval-driven interpolation ------------------
// One block per batch row. Inline batch min/max (redundant per block, L2-hot).
// Instead of per-point binary search, iterate over the N-1 x-intervals; the
// uniform common grid lets each interval locate its m-range in O(1). The
// predicate (xc > x[i-1] && xc <= x[i]) with a single deterministic xc formula
// partitions all m exactly once across intervals (== searchsorted 'left').
__global__ __launch_bounds__(256) void interp_kernel(
    const float* __restrict__ x,
    const float* __restrict__ y1,
    const float* __restrict__ y2,
    int N)
{
    __shared__ float red1[8], red2[8];
    __shared__ float s_minmax[2];

    const int b   = blockIdx.x;
    const int B   = gridDim.x;
    const int tid = threadIdx.x;
    const int lane = tid & 31, wid = tid >> 5;

    // ---- inline batch min/max over row endpoints (L2-resident after blk 0)
    {
        float mn = INFINITY, mx = -INFINITY;
        for (int r = tid; r < B; r += 256) {
            mn = fminf(mn, __ldg(x + (size_t)r * N));
            mx = fmaxf(mx, __ldg(x + (size_t)r * N + (N - 1)));
        }
        #pragma unroll
        for (int o = 16; o > 0; o >>= 1) {
            mn = fminf(mn, __shfl_xor_sync(0xffffffffu, mn, o));
            mx = fmaxf(mx, __shfl_xor_sync(0xffffffffu, mx, o));
        }
        if (lane == 0) { red1[wid] = mn; red2[wid] = mx; }
        __syncthreads();
        if (tid == 0) {
            float a = INFINITY, c = -INFINITY;
            #pragma unroll
            for (int w = 0; w < 8; w++) { a = fminf(a, red1[w]); c = fmaxf(c, red2[w]); }
            s_minmax[0] = a; s_minmax[1] = c;
        }
        __syncthreads();
    }
    const float xmin  = s_minmax[0];
    const float range = s_minmax[1] - xmin;
    const float inv_m1   = 1.0f / (float)(M_C - 1);
    const float inv_step = (float)(M_C - 1) / range;

    const float* xr  = x  + (size_t)b * N;
    const float* y1r = y1 + (size_t)b * N;
    const float* y2r = y2 + (size_t)b * N;
    __nv_bfloat16* o1 = g_y1c + (size_t)b * MP;
    __nv_bfloat16* o2 = g_y2c + (size_t)b * MP;

    // ---- phase 1: zero-fill the row (incl. pad) ----
    {
        const uint4 z = {0u, 0u, 0u, 0u};
        uint4* p1 = (uint4*)o1;
        uint4* p2 = (uint4*)o2;
        for (int i = tid; i < MP * 2 / 16; i += 256) { p1[i] = z; p2[i] = z; }
    }
    __syncthreads();   // orders zero-fill global writes before fill-phase writes

    // ---- phase 2: interval scatter ----
    float s1 = 0.f, s2 = 0.f;
    for (int i = tid; i < N; i += 256) {
        if (i == 0) {
            // only xc == x[0] survives the mask at the left edge -> y[0], w=0
            const float xv = __ldg(xr);
            int m = max(0, (int)((xv - xmin) * inv_step) - 2);
            for (int k = 0; k < 6 && m < M_C; k++, m++) {
                if (xc_of(m, xmin, range, inv_m1) == xv) {
                    float v1 = __ldg(y1r), v2 = __ldg(y2r);
                    o1[m] = __float2bfloat16(v1);
                    o2[m] = __float2bfloat16(v2);
                    s1 += v1 * v1; s2 += v2 * v2;
                }
            }
        } else {
            const float lo_v = __ldg(xr + i - 1);
            const float hi_v = __ldg(xr + i);
            int m = (int)fmaxf(0.f, (lo_v - xmin) * inv_step - 2.0f);
            #pragma unroll 1
            for (; m < M_C; m++) {
                const float xc = xc_of(m, xmin, range, inv_m1);
                if (xc > hi_v) break;
                if (xc > lo_v) {
                    float denom = hi_v - lo_v;
                    if (denom == 0.f) denom = 1.f;
                    float w = fminf(fmaxf((xc - lo_v) / (denom + 1e-9f), 0.f), 1.f);
                    float a1 = __ldg(y1r + i - 1), b1 = __ldg(y1r + i);
                    float a2 = __ldg(y2r + i - 1), b2 = __ldg(y2r + i);
                    float v1 = __fmaf_rn(w, b1 - a1, a1);
                    float v2 = __fmaf_rn(w, b2 - a2, a2);
                    o1[m] = __float2bfloat16(v1);
                    o2[m] = __float2bfloat16(v2);
                    s1 += v1 * v1; s2 += v2 * v2;
                }
            }
        }
    }

    // ---- per-row sq means ----
    #pragma unroll
    for (int o = 16; o > 0; o >>= 1) {
        s1 += __shfl_xor_sync(0xffffffffu, s1, o);
        s2 += __shfl_xor_sync(0xffffffffu, s2, o);
    }
    __syncthreads();   // red1/red2 reuse
    if (lane == 0) { red1[wid] = s1; red2[wid] = s2; }
    __syncthreads();
    if (tid == 0) {
        float t1 = 0.f, t2 = 0.f;
        #pragma unroll
        for (int w = 0; w < 8; w++) { t1 += red1[w]; t2 += red2[w]; }
        g_sq1[b] = t1 * (1.0f / (float)M_C);
        g_sq2[b] = t2 * (1.0f / (float)M_C);
    }
}

// ---------------- kernel 2: bf16 tensor-core GEMM + fused loss epilogue ----
// C[i][j] = dot(y1c[i,:], y2c[j,:]) via mma.sync.m16n8k16.bf16 (fp32 accum).
// Block tile 128(M) x 64(N), BK=32, 8 warps (4x2), warp tile 32x32.
// 3-stage cp.async pipeline; smem rows padded to 80B -> conflict-free ldmatrix.
#define GBM 128
#define GBN 64
#define GBK 32
#define ROW_B 80                       // bytes per smem row (32 bf16 + pad)
#define SA_STAGE (GBM * ROW_B)         // 10240 B
#define SB_STAGE (GBN * ROW_B)         // 5120 B
#define NSTAGE 3
#define SB_BASE (NSTAGE * SA_STAGE)    // 30720
#define SMEM_TOT (SB_BASE + NSTAGE * SB_STAGE)  // 46080 B

__device__ __forceinline__ void cp16(uint32_t dst, const void* src) {
    asm volatile("cp.async.cg.shared.global [%0], [%1], 16;\n"
                 :: "r"(dst), "l"(src));
}
__device__ __forceinline__ void ldsm_x4(uint32_t addr, uint32_t& r0, uint32_t& r1,
                                        uint32_t& r2, uint32_t& r3) {
    asm volatile("ldmatrix.sync.aligned.m8n8.x4.shared.b16 {%0,%1,%2,%3}, [%4];\n"
                 : "=r"(r0), "=r"(r1), "=r"(r2), "=r"(r3) : "r"(addr));
}
__device__ __forceinline__ void mma16816(float* c, const uint32_t* a, const uint32_t* b) {
    asm volatile(
        "mma.sync.aligned.m16n8k16.row.col.f32.bf16.bf16.f32 "
        "{%0,%1,%2,%3}, {%4,%5,%6,%7}, {%8,%9}, {%0,%1,%2,%3};\n"
        : "+f"(c[0]), "+f"(c[1]), "+f"(c[2]), "+f"(c[3])
        : "r"(a[0]), "r"(a[1]), "r"(a[2]), "r"(a[3]), "r"(b[0]), "r"(b[1]));
}

__global__ __launch_bounds__(256, 1) void gemm_loss_kernel(float* __restrict__ out, int B) {
    __shared__ __align__(16) unsigned char smem[SMEM_TOT];
    const uint32_t smem_u = (uint32_t)__cvta_generic_to_shared(smem);

    const int tid  = threadIdx.x;
    const int warp = tid >> 5;
    const int lane = tid & 31;

    const __nv_bfloat16* Ag = g_y1c + (size_t)blockIdx.y * GBM * MP;
    const __nv_bfloat16* Bg = g_y2c + (size_t)blockIdx.x * GBN * MP;

    const int a_row0 = tid >> 2, a_c = tid & 3;

    const int nkb = MP / GBK;    // 94

    auto load_stage = [&](int st, int kb) {
        const int k0 = kb * GBK;
        cp16(smem_u + st * SA_STAGE + a_row0 * ROW_B + a_c * 16,
             Ag + (size_t)a_row0 * MP + k0 + a_c * 8);
        cp16(smem_u + st * SA_STAGE + (a_row0 + 64) * ROW_B + a_c * 16,
             Ag + (size_t)(a_row0 + 64) * MP + k0 + a_c * 8);
        cp16(smem_u + SB_BASE + st * SB_STAGE + a_row0 * ROW_B + a_c * 16,
             Bg + (size_t)a_row0 * MP + k0 + a_c * 8);
    };

    load_stage(0, 0); asm volatile("cp.async.commit_group;\n" ::);
    load_stage(1, 1); asm volatile("cp.async.commit_group;\n" ::);

    const int wm = (warp >> 1) * 32;
    const int wn = (warp & 1) * 32;
    const int lr = lane & 7, q = lane >> 3;

    const uint32_t a_addr_base = smem_u + (wm + lr + (q & 1) * 8) * ROW_B + (q >> 1) * 16;
    const uint32_t b_addr_base = smem_u + SB_BASE + (wn + lr + (q >> 1) * 8) * ROW_B + (q & 1) * 16;

    float acc[2][4][4];
    #pragma unroll
    for (int mf = 0; mf < 2; mf++)
        #pragma unroll
        for (int nf = 0; nf < 4; nf++)
            #pragma unroll
            for (int r = 0; r < 4; r++) acc[mf][nf][r] = 0.f;

    for (int kb = 0; kb < nkb; kb++) {
        asm volatile("cp.async.wait_group 1;\n" ::);
        __syncthreads();   // single barrier: orders prev compute vs next load
        if (kb + 2 < nkb) load_stage((kb + 2) % NSTAGE, kb + 2);
        asm volatile("cp.async.commit_group;\n" ::);

        const int st = kb % NSTAGE;
        const uint32_t aS = a_addr_base + st * SA_STAGE;
        const uint32_t bS = b_addr_base + st * SB_STAGE;

        #pragma unroll
        for (int s = 0; s < 2; s++) {
            uint32_t a[2][4], b[2][4];
            #pragma unroll
            for (int mf = 0; mf < 2; mf++)
                ldsm_x4(aS + (mf * 16) * ROW_B + s * 32,
                        a[mf][0], a[mf][1], a[mf][2], a[mf][3]);
            #pragma unroll
            for (int p = 0; p < 2; p++)
                ldsm_x4(bS + (p * 16) * ROW_B + s * 32,
                        b[p][0], b[p][1], b[p][2], b[p][3]);
            #pragma unroll
            for (int mf = 0; mf < 2; mf++)
                #pragma unroll
                for (int nf = 0; nf < 4; nf++) {
                    uint32_t bb[2] = { b[nf >> 1][(nf & 1) * 2],
                                       b[nf >> 1][(nf & 1) * 2 + 1] };
                    mma16816(acc[mf][nf], a[mf], bb);
                }
        }
    }

    // fused loss epilogue
    const float inv_m = 1.0f / (float)M_C;
    const int gm = blockIdx.y * GBM + wm;
    const int gn = blockIdx.x * GBN + wn;
    #pragma unroll
    for (int mf = 0; mf < 2; mf++) {
        #pragma unroll
        for (int h = 0; h < 2; h++) {
            const int i = gm + mf * 16 + (lane >> 2) + h * 8;
            const float s1 = g_sq1[i];
            const float base = s1 + g_sq2[i] + EPS_B;   // reference quirk: both i-indexed
            const float scale = 2.0f / base;
            #pragma unroll
            for (int nf = 0; nf < 4; nf++) {
                const int j = gn + nf * 8 + (lane & 3) * 2;
                float c0 = acc[mf][nf][h * 2 + 0];
                float c1 = acc[mf][nf][h * 2 + 1];
                float d0 = fmaxf(s1 + g_sq2[j]     - 2.0f * c0 * inv_m, 0.f);
                float d1 = fmaxf(s1 + g_sq2[j + 1] - 2.0f * c1 * inv_m, 0.f);
                float2 o = { sqrtf(d0 * scale), sqrtf(d1 * scale) };
                *(float2*)(out + (size_t)i * B + j) = o;
            }
        }
    }
}

// ---------------- launch ----------------
extern "C" void kernel_launch(void* const* d_in, const int* in_sizes, int n_in,
                              void* d_out, int out_size) {
    const float* x  = (const float*)d_in[0];
    const float* y1 = (const float*)d_in[1];
    const float* y2 = (const float*)d_in[2];
    float* out = (float*)d_out;

    // out is [B, B] -> exact integer sqrt
    int B = 1;
    while ((long long)(B + 1) * (B + 1) <= (long long)out_size) B++;
    int N = in_sizes[0] / B;

    interp_kernel<<<B, 256>>>(x, y1, y2, N);
    dim3 grid(B / GBN, B / GBM);   // (16, 8)
    gemm_loss_kernel<<<grid, 256>>>(out, B);
}